// round 16
// baseline (speedup 1.0000x reference)
#include <cuda_runtime.h>
#include <cuda_fp16.h>
#include <cstdint>

// gcnmask N=50000, DEG=16 (edge_dst = repeat(arange(N),16) structural), F=128.
// compute_103 PTX target: tcgen05 unavailable -> sm_80-baseline mma.sync.m16n8k16
// (fp16 in, fp32 acc), ldmatrix fragments, weights pre-transposed fp16 (k_prep).
// R16 = resubmission of R15 (container-infra failure, no data; R10/R11 precedent
// shows these are not kernel-determined).
// R15 change under test: 64-row tiles (782 blocks) for k_proj/k2 — at 2 CTAs/SM
// the old 391-block grids ran 2 full waves (66% util); finer tiles cut makespan
// 2T -> 1.5T. GEMM re-tiled to 16 warps x (16M x 32N), single A-fragment.
//
//   cproj = x @ Wm[0:128], nproj = x @ Wm[128:256]
//   agg[n] = sum_e sigmoid(cproj[n]+nproj[src]) * x[src];  x_new = x + agg
//   support = x_new @ W;  out[n] = bias + sum_e adj[e]*support[src]

#define NN 50000
#define FF 128
#define DEG 16
#define NT2 782           // ceil(50000/64) row tiles (last tile 16 rows)
#define STR 136           // smem row stride in halfs (272B) -> conflict-free frags
#define MATH (128 * STR)  // halfs per weight tile
#define SM1 ((64 + 256) * STR * 2)    // k_proj: A(64) + both Wm halves
#define SM2 ((64 + 128) * STR * 2)    // k2:     A(64) + W
#define R3 16

__device__ __align__(16) __half  g_cph[NN * FF];  // cproj fp16
__device__ __align__(16) __half2 g_xn2[NN * FF];  // {x, nproj} — K2 gather stream
__device__ __align__(16) __half  g_sup[NN * FF];  // support fp16 — K3 gather stream
__device__ __align__(16) __half  g_B[3 * MATH];   // WmTop^T, WmBot^T, W^T  [n][k]

// ---- helpers ----
__device__ __forceinline__ float tanh_approx(float z) {
    float r; asm("tanh.approx.f32 %0, %1;" : "=f"(r) : "f"(z)); return r;
}
__device__ __forceinline__ unsigned smem_u32(const void* p) {
    unsigned r;
    asm("{ .reg .u64 t; cvta.to.shared.u64 t, %1; cvt.u32.u64 %0, t; }" : "=r"(r) : "l"(p));
    return r;
}
__device__ __forceinline__ void ldmat4(uint32_t& r0, uint32_t& r1, uint32_t& r2,
                                       uint32_t& r3, unsigned addr) {
    asm volatile("ldmatrix.sync.aligned.m8n8.x4.shared.b16 {%0,%1,%2,%3}, [%4];"
                 : "=r"(r0), "=r"(r1), "=r"(r2), "=r"(r3) : "r"(addr));
}
__device__ __forceinline__ void mma16816(float& d0, float& d1, float& d2, float& d3,
                                         uint32_t a0, uint32_t a1, uint32_t a2, uint32_t a3,
                                         uint32_t b0, uint32_t b1) {
    asm volatile(
        "mma.sync.aligned.m16n8k16.row.col.f32.f16.f16.f32 "
        "{%0,%1,%2,%3}, {%4,%5,%6,%7}, {%8,%9}, {%0,%1,%2,%3};"
        : "+f"(d0), "+f"(d1), "+f"(d2), "+f"(d3)
        : "r"(a0), "r"(a1), "r"(a2), "r"(a3), "r"(b0), "r"(b1));
}

// 16 warps, warp tile 16(M) x 32(N), K=128. As[r][k], Bs[n][k], stride STR.
// AADDR: single ldmatrix.x4 base (rows mb+(lane&15), col (lane>>4)*8).
// BADDR[p]: B pair p -> nt = 2p, 2p+1.  acc[nt][4].
#define GEMM_BODY16(AADDR, BADDR, ACC)                                         \
    _Pragma("unroll")                                                          \
    for (int ks = 0; ks < 8; ++ks) {                                           \
        const int kb = ks * 32;                                                \
        uint32_t a0, a1, a2, a3;                                               \
        ldmat4(a0, a1, a2, a3, (AADDR) + kb);                                  \
        _Pragma("unroll")                                                      \
        for (int p = 0; p < 2; ++p) {                                          \
            uint32_t b00, b01, b10, b11;                                       \
            ldmat4(b00, b01, b10, b11, (BADDR)[p] + kb);                       \
            mma16816(ACC[2 * p][0], ACC[2 * p][1], ACC[2 * p][2],              \
                     ACC[2 * p][3], a0, a1, a2, a3, b00, b01);                 \
            mma16816(ACC[2 * p + 1][0], ACC[2 * p + 1][1], ACC[2 * p + 1][2],  \
                     ACC[2 * p + 1][3], a0, a1, a2, a3, b10, b11);             \
        }                                                                      \
    }

// ============================================================================
// K0: one-time weight transpose to fp16 [n][k] stride-STR tiles.
// ============================================================================
__global__ __launch_bounds__(256) void k_prep(const float* __restrict__ w,
                                              const float* __restrict__ wm) {
    const int idx = blockIdx.x * 256 + threadIdx.x;   // 192 blocks = 49152
    const int m = idx >> 14, r = idx & 16383;
    const int k = r >> 7, n = r & 127;
    float v;
    if (m == 0)      v = __ldg(&wm[k * FF + n]);
    else if (m == 1) v = __ldg(&wm[(FF + k) * FF + n]);
    else             v = __ldg(&w[k * FF + n]);
    g_B[m * MATH + n * STR + k] = __float2half_rn(v);
}

// ============================================================================
// K1: 64-row A tile; both Wm halves resident; GEMM h=0 -> cproj fp16,
// h=1 -> g_xn2 {x,nproj} (uint2 coalesced stores).
// ============================================================================
__global__ __launch_bounds__(512, 2) void k_proj_mma(const float* __restrict__ x) {
    extern __shared__ __half sm[];
    __half* As = sm;                 // [64][STR]
    __half* Bs = sm + 64 * STR;      // [256][STR]: h=0 rows 0-127, h=1 rows 128-255
    const int tid = threadIdx.x;
    const int row0 = blockIdx.x * 64;

    {   // B: both prepped Wm tiles (4352 uint4)
        uint4* dst = (uint4*)Bs;
        const uint4* src = (const uint4*)g_B;
#pragma unroll
        for (int i = 0; i < 9; ++i) {
            const int idx = i * 512 + tid;
            if (idx < 4352) dst[idx] = src[idx];
        }
    }
    {   // A: 64x128 halfs via float4 x loads (2048 quads)
#pragma unroll
        for (int i = 0; i < 4; ++i) {
            const int idx = i * 512 + tid;
            const int r = idx >> 5, c4 = (idx & 31) * 4;
            const int row = row0 + r;
            float4 v = make_float4(0.f, 0.f, 0.f, 0.f);
            if (row < NN) v = *(const float4*)&x[row * FF + c4];
            __half2 lo = __floats2half2_rn(v.x, v.y);
            __half2 hi = __floats2half2_rn(v.z, v.w);
            *(uint2*)&As[r * STR + c4] = make_uint2(*(uint32_t*)&lo, *(uint32_t*)&hi);
        }
    }
    __syncthreads();

    const int warp = tid >> 5, lane = tid & 31;
    const int wr = warp >> 2, wc = warp & 3;
    const int mb = wr * 16, nb = wc * 32;
    const int g = lane >> 2, t = lane & 3, q = lane >> 3;

    const unsigned As32 = smem_u32(As);
    const unsigned Bs32 = smem_u32(Bs);
    const unsigned aaddr =
        As32 + ((mb + (lane & 15)) * STR + (lane >> 4) * 8) * 2;
    const int brow_l = (lane & 7) + (q >> 1) * 8;
    const int bcol_l = (q & 1) * 8;

    unsigned baddr[2];
    float acc[4][4];
#pragma unroll
    for (int h = 0; h < 2; ++h) {
#pragma unroll
        for (int p = 0; p < 2; ++p)
            baddr[p] = Bs32 + ((h * 128 + nb + p * 16 + brow_l) * STR + bcol_l) * 2;
#pragma unroll
        for (int nt = 0; nt < 4; ++nt)
#pragma unroll
            for (int c = 0; c < 4; ++c) acc[nt][c] = 0.f;

        GEMM_BODY16(aaddr, baddr, acc)

        const int rl = mb + g;            // local rows rl, rl+8
        const int rA = row0 + rl;
#pragma unroll
        for (int nt = 0; nt < 4; ++nt) {
            const int col = nb + nt * 8 + 2 * t;
            if (h == 0) {
                if (rA < NN) {
                    const __half2 hv = __floats2half2_rn(acc[nt][0], acc[nt][1]);
                    *(uint32_t*)&g_cph[rA * FF + col] = *(const uint32_t*)&hv;
                }
                if (rA + 8 < NN) {
                    const __half2 hv = __floats2half2_rn(acc[nt][2], acc[nt][3]);
                    *(uint32_t*)&g_cph[(rA + 8) * FF + col] = *(const uint32_t*)&hv;
                }
            } else {
                if (rA < NN) {
                    const uint32_t xa = *(uint32_t*)&As[rl * STR + col];
                    __half2 v0, v1;
                    v0.x = ((const __half2*)&xa)->x;
                    v0.y = __float2half_rn(acc[nt][0]);
                    v1.x = ((const __half2*)&xa)->y;
                    v1.y = __float2half_rn(acc[nt][1]);
                    *(uint2*)&g_xn2[rA * FF + col] =
                        make_uint2(*(uint32_t*)&v0, *(uint32_t*)&v1);
                }
                if (rA + 8 < NN) {
                    const uint32_t xa = *(uint32_t*)&As[(rl + 8) * STR + col];
                    __half2 v2, v3;
                    v2.x = ((const __half2*)&xa)->x;
                    v2.y = __float2half_rn(acc[nt][2]);
                    v3.x = ((const __half2*)&xa)->y;
                    v3.y = __float2half_rn(acc[nt][3]);
                    *(uint2*)&g_xn2[(rA + 8) * FF + col] =
                        make_uint2(*(uint32_t*)&v2, *(uint32_t*)&v3);
                }
            }
        }
    }
}

// ============================================================================
// K2: 64-row tile. Edge gather (uint4 16B loads, batched int4 indices) ->
// x_new fp16 into As, then support = x_new @ W.
// ============================================================================
__global__ __launch_bounds__(512, 2) void k_agg_support(const float* __restrict__ x,
                                                        const int* __restrict__ esrc) {
    extern __shared__ __half sm[];
    __half* As = sm;                 // [64][STR]
    __half* Bs = sm + 64 * STR;      // [128][STR]
    const int tid = threadIdx.x;
    const int row0 = blockIdx.x * 64;

    {   // B: prepped W^T tile (2176 uint4)
        uint4* dst = (uint4*)Bs;
        const uint4* src = (const uint4*)(g_B + 2 * MATH);
#pragma unroll
        for (int i = 0; i < 5; ++i) {
            const int idx = i * 512 + tid;
            if (idx < 2176) dst[idx] = src[idx];
        }
    }

    // Gather: thread = (col-quad c4 = lane, row-group rg); 4 rows per thread.
    const int c4 = tid & 31, rg = tid >> 5;
#pragma unroll
    for (int i = 0; i < 4; ++i) {
        const int r = rg * 4 + i;
        const int n = row0 + r;
        float4 v = make_float4(0.f, 0.f, 0.f, 0.f);
        if (n < NN) {
            const uint2 cpu = *(const uint2*)&g_cph[n * FF + 4 * c4];
            const float2 cpa = __half22float2(*(const __half2*)&cpu.x);
            const float2 cpb = __half22float2(*(const __half2*)&cpu.y);
            const int4* ep = (const int4*)(esrc + n * DEG);
            int sidx[16];
#pragma unroll
            for (int b = 0; b < 4; ++b) {
                const int4 e4 = __ldg(&ep[b]);
                sidx[4 * b] = e4.x; sidx[4 * b + 1] = e4.y;
                sidx[4 * b + 2] = e4.z; sidx[4 * b + 3] = e4.w;
            }
            float a0 = 0.f, a1 = 0.f, a2 = 0.f, a3 = 0.f;
#pragma unroll
            for (int e = 0; e < DEG; ++e) {
                const uint4 u = *(const uint4*)&g_xn2[sidx[e] * FF + 4 * c4];  // 16B
                const float2 f0 = __half22float2(*(const __half2*)&u.x);
                const float2 f1 = __half22float2(*(const __half2*)&u.y);
                const float2 f2 = __half22float2(*(const __half2*)&u.z);
                const float2 f3 = __half22float2(*(const __half2*)&u.w);
                a0 = fmaf(fmaf(0.5f, tanh_approx(0.5f * (cpa.x + f0.y)), 0.5f), f0.x, a0);
                a1 = fmaf(fmaf(0.5f, tanh_approx(0.5f * (cpa.y + f1.y)), 0.5f), f1.x, a1);
                a2 = fmaf(fmaf(0.5f, tanh_approx(0.5f * (cpb.x + f2.y)), 0.5f), f2.x, a2);
                a3 = fmaf(fmaf(0.5f, tanh_approx(0.5f * (cpb.y + f3.y)), 0.5f), f3.x, a3);
            }
            const float4 xv = *(const float4*)&x[n * FF + 4 * c4];
            v = make_float4(xv.x + a0, xv.y + a1, xv.z + a2, xv.w + a3);
        }
        const __half2 h0 = __floats2half2_rn(v.x, v.y);
        const __half2 h1 = __floats2half2_rn(v.z, v.w);
        *(uint2*)&As[r * STR + 4 * c4] =
            make_uint2(*(const uint32_t*)&h0, *(const uint32_t*)&h1);
    }
    __syncthreads();

    const int warp = tid >> 5, lane = tid & 31;
    const int wr = warp >> 2, wc = warp & 3;
    const int mb = wr * 16, nb = wc * 32;
    const int g = lane >> 2, t = lane & 3, q = lane >> 3;

    const unsigned As32 = smem_u32(As);
    const unsigned Bs32 = smem_u32(Bs);
    const unsigned aaddr =
        As32 + ((mb + (lane & 15)) * STR + (lane >> 4) * 8) * 2;
    unsigned baddr[2];
#pragma unroll
    for (int p = 0; p < 2; ++p)
        baddr[p] = Bs32 +
                   ((nb + p * 16 + (lane & 7) + (q >> 1) * 8) * STR + (q & 1) * 8) * 2;

    float acc[4][4];
#pragma unroll
    for (int nt = 0; nt < 4; ++nt)
#pragma unroll
        for (int c = 0; c < 4; ++c) acc[nt][c] = 0.f;

    GEMM_BODY16(aaddr, baddr, acc)

    const int rA = row0 + mb + g;
#pragma unroll
    for (int nt = 0; nt < 4; ++nt) {
        const int col = nb + nt * 8 + 2 * t;
        if (rA < NN)
            *(__half2*)&g_sup[rA * FF + col] =
                __floats2half2_rn(acc[nt][0], acc[nt][1]);
        if (rA + 8 < NN)
            *(__half2*)&g_sup[(rA + 8) * FF + col] =
                __floats2half2_rn(acc[nt][2], acc[nt][3]);
    }
}

// ============================================================================
// K3: out[n] = bias + sum_e adj[e]*support[src].  uint4 gathers + batched
// index/adj loads.  (at L2-sector floor; unchanged)
// ============================================================================
__global__ __launch_bounds__(256) void k_out(const float* __restrict__ adj,
                                             const int* __restrict__ esrc,
                                             const float* __restrict__ bias,
                                             float* __restrict__ out) {
    const int tid = threadIdx.x;
    const int c8 = tid & 15, r = tid >> 4;
    const int n = blockIdx.x * R3 + r;
    const float4 b0 = *(const float4*)&bias[8 * c8];
    const float4 b1 = *(const float4*)&bias[8 * c8 + 4];

    const int4* ep = (const int4*)(esrc + n * DEG);
    const float4* ap = (const float4*)(adj + n * DEG);
    int sidx[16];
    float aw[16];
#pragma unroll
    for (int b = 0; b < 4; ++b) {
        const int4 e4 = __ldg(&ep[b]);
        const float4 a4 = __ldg(&ap[b]);
        sidx[4 * b] = e4.x; sidx[4 * b + 1] = e4.y;
        sidx[4 * b + 2] = e4.z; sidx[4 * b + 3] = e4.w;
        aw[4 * b] = a4.x; aw[4 * b + 1] = a4.y;
        aw[4 * b + 2] = a4.z; aw[4 * b + 3] = a4.w;
    }

    float4 o0 = b0, o1 = b1;
#pragma unroll
    for (int e = 0; e < DEG; ++e) {
        const float a = aw[e];
        const uint4 u = *(const uint4*)&g_sup[sidx[e] * FF + 8 * c8];   // 16B gather
        const float2 f0 = __half22float2(*(const __half2*)&u.x);
        const float2 f1 = __half22float2(*(const __half2*)&u.y);
        const float2 f2 = __half22float2(*(const __half2*)&u.z);
        const float2 f3 = __half22float2(*(const __half2*)&u.w);
        o0.x = fmaf(a, f0.x, o0.x); o0.y = fmaf(a, f0.y, o0.y);
        o0.z = fmaf(a, f1.x, o0.z); o0.w = fmaf(a, f1.y, o0.w);
        o1.x = fmaf(a, f2.x, o1.x); o1.y = fmaf(a, f2.y, o1.y);
        o1.z = fmaf(a, f3.x, o1.z); o1.w = fmaf(a, f3.y, o1.w);
    }
    *(float4*)&out[n * FF + 8 * c8] = o0;
    *(float4*)&out[n * FF + 8 * c8 + 4] = o1;
}

// ============================================================================
extern "C" void kernel_launch(void* const* d_in, const int* in_sizes, int n_in,
                              void* d_out, int out_size) {
    const float* x    = (const float*)d_in[0];  // [N,128]
    const float* w    = (const float*)d_in[1];  // [128,128]
    const float* bias = (const float*)d_in[2];  // [128]
    const float* wm   = (const float*)d_in[3];  // [256,128]
    const float* adj  = (const float*)d_in[4];  // [E]
    const int*   esrc = (const int*)d_in[5];    // [E]
    float* out = (float*)d_out;

    cudaFuncSetAttribute(k_proj_mma, cudaFuncAttributeMaxDynamicSharedMemorySize, SM1);
    cudaFuncSetAttribute(k_agg_support, cudaFuncAttributeMaxDynamicSharedMemorySize, SM2);

    k_prep<<<192, 256>>>(w, wm);
    k_proj_mma<<<NT2, 512, SM1>>>(x);
    k_agg_support<<<NT2, 512, SM2>>>(x, esrc);
    k_out<<<NN / R3, 256>>>(adj, esrc, bias, out);
}